// round 1
// baseline (speedup 1.0000x reference)
#include <cuda_runtime.h>

#define NB 512   // batch
#define NN 128   // nodes
#define ND 256   // feature dim
#define NT 512   // head length

#define SP 129   // pitch for S / T1 tiles in smem (conflict-free: 129 % 32 == 1)
#define XP 65    // pitch for X tile (65 % 32 == 1)
#define XW 64    // X tile width

// Scratch for assignment matrix S (32 MB) — __device__ global, no allocation.
__device__ float g_S[(size_t)NB * NN * NN];

// ---------------------------------------------------------------------------
// Kernel A: one CTA per batch. Computes alpha, cut threshold, and the
// row-L1-normalized S matrix, writing S to g_S. adj[b] cached in SMEM.
// ---------------------------------------------------------------------------
__global__ __launch_bounds__(256) void kA(
    const float* __restrict__ x, const float* __restrict__ adj,
    const int* __restrict__ head, const float* __restrict__ lw,
    const float* __restrict__ bias)
{
    extern __shared__ float adj_sh[];  // NN*NN floats (64 KB)
    __shared__ float sh_w[ND];
    __shared__ float sh_v[NN], sh_rs[NN], sh_dinv[NN], sh_coef[NN], sh_dv[NN];
    __shared__ float sh_alpha[NN], sh_ca[NN];
    __shared__ int   sh_flags[NN];
    __shared__ float sh_cut;

    const int b = blockIdx.x, tid = threadIdx.x;
    const int lane = tid & 31, w = tid >> 5;
    const float* xb = x + (size_t)b * NN * ND;
    const float* ab = adj + (size_t)b * NN * NN;

    for (int u = tid; u < NN * NN; u += 256) adj_sh[u] = ab[u];
    if (tid < ND) sh_w[tid] = lw[tid];
    if (tid < NN) sh_flags[tid] = 0;
    if (tid == 0) sh_cut = 0.f;
    __syncthreads();

    // mark unique head indices (idempotent racy writes are fine)
    sh_flags[head[(size_t)b * NT + tid] & (NN - 1)] = 1;
    sh_flags[head[(size_t)b * NT + tid + 256] & (NN - 1)] = 1;

    // v[n] = x[n,:] . lin_w   and   rowsum[n] = sum_j adj[n,j]
    for (int n = w; n < NN; n += 8) {
        float s = 0.f, r = 0.f;
        #pragma unroll
        for (int q = 0; q < ND / 32; ++q) s += xb[n * ND + lane + q * 32] * sh_w[lane + q * 32];
        #pragma unroll
        for (int q = 0; q < NN / 32; ++q) r += adj_sh[n * NN + lane + q * 32];
        #pragma unroll
        for (int o = 16; o; o >>= 1) {
            s += __shfl_down_sync(0xffffffffu, s, o);
            r += __shfl_down_sync(0xffffffffu, r, o);
        }
        if (!lane) { sh_v[n] = s; sh_rs[n] = r; }
    }
    __syncthreads();

    if (tid < NN) {
        float r  = sh_rs[tid];
        float di = rsqrtf(fmaxf(r + 1.f, 1.f));  // A = adj + I → deg = rowsum + 1
        sh_dinv[tid] = di;
        sh_coef[tid] = (r > 0.f) ? di : 0.f;     // row_mask * dinv
        sh_dv[tid]   = di * sh_v[tid];
    }
    __syncthreads();

    // out_i = coef_i * (sum_j adj_ij * dv_j + dv_i) + bias ; alpha = sigmoid(out^2)
    const float bia = bias[0];
    for (int i = w; i < NN; i += 8) {
        float t = 0.f;
        #pragma unroll
        for (int q = 0; q < NN / 32; ++q) t += adj_sh[i * NN + lane + q * 32] * sh_dv[lane + q * 32];
        #pragma unroll
        for (int o = 16; o; o >>= 1) t += __shfl_down_sync(0xffffffffu, t, o);
        if (!lane) {
            t += sh_dv[i];
            float o1 = sh_coef[i] * t + bia;
            float o2 = o1 * o1;
            sh_alpha[i] = 1.f / (1.f + __expf(-o2));
        }
    }

    // unique count + barrier (flags all written before the prior two barriers)
    const int nuniq = __syncthreads_count((tid < NN) ? sh_flags[tid] : 0);

    // cut = (k-th largest alpha) with tie-correct descending-sort semantics
    if (nuniq > 1 && tid < NN) {
        float a = sh_alpha[tid];
        int gt = 0, ge = 0;
        for (int j = 0; j < NN; ++j) {
            float aj = sh_alpha[j];
            gt += (aj > a);
            ge += (aj >= a);
        }
        int k   = (nuniq + 9) / 10 + 1;   // ceil(n*0.1) + 1
        int idx = min(k - 1, NN - 1);
        if (gt <= idx && idx < ge) sh_cut = a;
    }
    __syncthreads();
    if (tid < NN) sh_ca[tid] = fmaxf(sh_alpha[tid] + 1e-7f - sh_cut, 0.f);
    __syncthreads();

    // S rows: S_ij = coef_i * (adj_ij + I_ij) * dinv_j * ca_j, row-L1-normalized
    float* Sb = g_S + (size_t)b * NN * NN;
    for (int i = w; i < NN; i += 8) {
        float c = sh_coef[i];
        float vals[4], s = 0.f;
        #pragma unroll
        for (int q = 0; q < 4; ++q) {
            int j = lane + q * 32;
            float a = adj_sh[i * NN + j] + ((j == i) ? 1.f : 0.f);
            float v = c * a * sh_dinv[j] * sh_ca[j];
            vals[q] = v;
            s += v;
        }
        #pragma unroll
        for (int o = 16; o; o >>= 1) s += __shfl_xor_sync(0xffffffffu, s, o);
        float inv = 1.f / fmaxf(s, 1e-12f);   // all terms nonneg ⇒ L1 == sum
        #pragma unroll
        for (int q = 0; q < 4; ++q) Sb[i * NN + lane + q * 32] = vals[q] * inv;
    }
}

// ---------------------------------------------------------------------------
// Kernel BC: one CTA per batch. S in SMEM; computes T1 = S^T adj (SMEM only),
// emb = S^T x (stores staged via SMEM for coalescing), new_adj = T1 @ S.
// Register blocking 4x8 keeps LDS wavefronts below the FFMA rt floor.
// ---------------------------------------------------------------------------
__global__ __launch_bounds__(256) void kBC(
    const float* __restrict__ x, const float* __restrict__ adj,
    float* __restrict__ emb, float* __restrict__ nadj)
{
    extern __shared__ float sm[];
    float* Ssh = sm;                 // NN * SP
    float* T1  = sm + NN * SP;       // NN * SP
    float* Xsh = sm + 2 * NN * SP;   // NN * XP

    const int b = blockIdx.x, tid = threadIdx.x;
    const float* Sg = g_S + (size_t)b * NN * NN;
    const float* ab = adj + (size_t)b * NN * NN;
    const float* xb = x + (size_t)b * NN * ND;

    for (int u = tid; u < NN * NN; u += 256)
        Ssh[(u >> 7) * SP + (u & 127)] = Sg[u];
    __syncthreads();

    const int ngrp = tid & 31;   // owns n in {ngrp, ngrp+32, ngrp+64, ngrp+96}
    const int dg   = tid >> 5;   // 0..7 → d offset dg*8 within 64-wide tile

    // ---- Phase 1: T1 = S^T adj (2 column tiles of 64, result stays in SMEM)
    #pragma unroll
    for (int t = 0; t < NN / XW; ++t) {
        int j0 = t * XW;
        for (int u = tid; u < NN * XW; u += 256) {
            int m = u >> 6, dd = u & 63;
            Xsh[m * XP + dd] = ab[m * NN + j0 + dd];
        }
        __syncthreads();
        float acc[4][8];
        #pragma unroll
        for (int k = 0; k < 4; ++k)
            #pragma unroll
            for (int c = 0; c < 8; ++c) acc[k][c] = 0.f;
        for (int m = 0; m < NN; ++m) {
            float xv[8];
            #pragma unroll
            for (int c = 0; c < 8; ++c) xv[c] = Xsh[m * XP + dg * 8 + c];
            #pragma unroll
            for (int k = 0; k < 4; ++k) {
                float s = Ssh[m * SP + ngrp + 32 * k];
                #pragma unroll
                for (int c = 0; c < 8; ++c) acc[k][c] = fmaf(s, xv[c], acc[k][c]);
            }
        }
        #pragma unroll
        for (int k = 0; k < 4; ++k)
            #pragma unroll
            for (int c = 0; c < 8; ++c)
                T1[(ngrp + 32 * k) * SP + j0 + dg * 8 + c] = acc[k][c];
        __syncthreads();
    }

    // ---- Phase 2: emb = S^T x (4 tiles of 64; stores staged through SMEM)
    #pragma unroll
    for (int t = 0; t < ND / XW; ++t) {
        int d0 = t * XW;
        for (int u = tid; u < NN * XW; u += 256) {
            int m = u >> 6, dd = u & 63;
            Xsh[m * XP + dd] = xb[m * ND + d0 + dd];
        }
        __syncthreads();
        float acc[4][8];
        #pragma unroll
        for (int k = 0; k < 4; ++k)
            #pragma unroll
            for (int c = 0; c < 8; ++c) acc[k][c] = 0.f;
        for (int m = 0; m < NN; ++m) {
            float xv[8];
            #pragma unroll
            for (int c = 0; c < 8; ++c) xv[c] = Xsh[m * XP + dg * 8 + c];
            #pragma unroll
            for (int k = 0; k < 4; ++k) {
                float s = Ssh[m * SP + ngrp + 32 * k];
                #pragma unroll
                for (int c = 0; c < 8; ++c) acc[k][c] = fmaf(s, xv[c], acc[k][c]);
            }
        }
        __syncthreads();  // all reads of Xsh done before repurposing it
        #pragma unroll
        for (int k = 0; k < 4; ++k)
            #pragma unroll
            for (int c = 0; c < 8; ++c)
                Xsh[(ngrp + 32 * k) * XP + dg * 8 + c] = acc[k][c];
        __syncthreads();
        for (int u = tid; u < NN * XW; u += 256) {
            int m = u >> 6, dd = u & 63;
            emb[(size_t)b * NN * ND + m * ND + d0 + dd] = Xsh[m * XP + dd];
        }
        __syncthreads();  // stores read Xsh before next tile overwrites it
    }

    // ---- Phase 3: new_adj = T1 @ S (thread owns j∈{jp,jp+64}, 8 i's per chunk)
    const int jp = tid & 63, ih = tid >> 6;
    #pragma unroll
    for (int cch = 0; cch < 4; ++cch) {
        int i0 = ih * 32 + cch * 8;
        float a0[8], a1[8];
        #pragma unroll
        for (int ii = 0; ii < 8; ++ii) { a0[ii] = 0.f; a1[ii] = 0.f; }
        for (int m = 0; m < NN; ++m) {
            float s0 = Ssh[m * SP + jp];
            float s1 = Ssh[m * SP + jp + 64];
            #pragma unroll
            for (int ii = 0; ii < 8; ++ii) {
                float t1 = T1[(i0 + ii) * SP + m];
                a0[ii] = fmaf(t1, s0, a0[ii]);
                a1[ii] = fmaf(t1, s1, a1[ii]);
            }
        }
        #pragma unroll
        for (int ii = 0; ii < 8; ++ii) {
            nadj[(size_t)b * NN * NN + (i0 + ii) * NN + jp]      = a0[ii];
            nadj[(size_t)b * NN * NN + (i0 + ii) * NN + jp + 64] = a1[ii];
        }
    }
}

extern "C" void kernel_launch(void* const* d_in, const int* in_sizes, int n_in,
                              void* d_out, int out_size) {
    const float* x    = (const float*)d_in[0];
    const float* adj  = (const float*)d_in[1];
    const int*   head = (const int*)d_in[2];
    const float* lw   = (const float*)d_in[3];
    const float* bias = (const float*)d_in[4];

    float* out  = (float*)d_out;
    float* emb  = out;                               // [B, N, D]
    float* nadj = out + (size_t)NB * NN * ND;        // [B, N, N]

    const int smemA  = NN * NN * 4;                                  // 64 KB
    const int smemBC = (2 * NN * SP + NN * XP) * 4;                  // ~161.5 KB

    cudaFuncSetAttribute(kA,  cudaFuncAttributeMaxDynamicSharedMemorySize, smemA);
    cudaFuncSetAttribute(kBC, cudaFuncAttributeMaxDynamicSharedMemorySize, smemBC);

    kA<<<NB, 256, smemA>>>(x, adj, head, lw, bias);
    kBC<<<NB, 256, smemBC>>>(x, adj, emb, nadj);
}

// round 3
// speedup vs baseline: 2.0076x; 2.0076x over previous
#include <cuda_runtime.h>
#include <cstdint>

#define NB 512
#define NN 128
#define ND 256
#define NTH 512
#define PS 132   // SshT pitch (floats): 132 % 32 == 4  -> frag bank = 4g+tg (distinct)
#define PA 136   // adj/X pitch (floats): 136 % 32 == 8 -> frag bank = 8tg+g (distinct)
#define PT 132   // T1 pitch (reuses adj buffer)

static __device__ __forceinline__ float tf32r(float f){
    uint32_t r;
    asm("cvt.rna.tf32.f32 %0, %1;" : "=r"(r) : "f"(f));
    return __uint_as_float(r);
}

#define MMA8(C, A, B0, B1) \
    asm volatile("mma.sync.aligned.m16n8k8.row.col.f32.tf32.tf32.f32 " \
        "{%0,%1,%2,%3}, {%4,%5,%6,%7}, {%8,%9}, {%0,%1,%2,%3};" \
        : "+f"((C)[0]), "+f"((C)[1]), "+f"((C)[2]), "+f"((C)[3]) \
        : "r"((A)[0]), "r"((A)[1]), "r"((A)[2]), "r"((A)[3]), "r"(B0), "r"(B1))

__global__ __launch_bounds__(256, 1) void kmain(
    const float* __restrict__ x, const float* __restrict__ adj,
    const int* __restrict__ head, const float* __restrict__ lw,
    const float* __restrict__ bias, float* __restrict__ emb, float* __restrict__ nadj)
{
    extern __shared__ float sm[];
    float* Ssh = sm;               // SshT[i][m] = S[m][i], tf32, pitch PS
    float* AB  = sm + NN * PS;     // adj fp32 (pitch PA) -> later T1 tf32 (pitch PT)
    float* XB  = AB + NN * PA;     // X tile [128 rows][128 cols], tf32, pitch PA

    __shared__ float sh_w[ND];
    __shared__ float sh_dinv[NN], sh_coef[NN], sh_dv[NN], sh_alpha[NN], sh_ca[NN];
    __shared__ int   sh_flags[NN];
    __shared__ float sh_cut;

    const int b = blockIdx.x, tid = threadIdx.x;
    const int lane = tid & 31, wid = tid >> 5;
    const int g = lane >> 2, tg = lane & 3;          // mma fragment coords
    const int ih = wid >> 1, jh = wid & 1;           // warp tile: rows ih*32, cols jh*64
    const int i0 = ih * 32;

    const float* xb = x + (size_t)b * NN * ND;
    const float* ab = adj + (size_t)b * NN * NN;

    // ---- loads: adj (fp32), X tile 0 (tf32), weights, flag init ----
    for (int u = tid; u < NN * NN; u += 256) AB[(u >> 7) * PA + (u & 127)] = ab[u];
    for (int u = tid; u < NN * 128; u += 256){
        int m = u >> 7, d = u & 127;
        XB[m * PA + d] = tf32r(xb[m * ND + d]);
    }
    sh_w[tid] = lw[tid];
    if (tid < NN) sh_flags[tid] = 0;
    if (tid == 0) sh_cut = 0.f;
    __syncthreads();

    // unique-head marking (idempotent racy writes)
    sh_flags[head[(size_t)b * NTH + tid]       & (NN - 1)] = 1;
    sh_flags[head[(size_t)b * NTH + tid + 256] & (NN - 1)] = 1;

    // ---- rowsum_r, v_r = x[r]·w ----
    for (int r = wid; r < NN; r += 8){
        float s = 0.f, rs = 0.f;
        #pragma unroll
        for (int q = 0; q < 8; ++q) s += xb[r * ND + lane + q * 32] * sh_w[lane + q * 32];
        #pragma unroll
        for (int q = 0; q < 4; ++q) rs += AB[r * PA + lane + q * 32];
        #pragma unroll
        for (int o = 16; o; o >>= 1){
            s  += __shfl_down_sync(~0u, s, o);
            rs += __shfl_down_sync(~0u, rs, o);
        }
        if (!lane){
            float di = rsqrtf(fmaxf(rs + 1.f, 1.f));
            sh_dinv[r] = di;
            sh_coef[r] = (rs > 0.f) ? di : 0.f;
            sh_dv[r]   = di * s;
        }
    }
    __syncthreads();

    // ---- alpha_r = sigmoid((coef_r*(adj[r]·dv + dv_r) + bias)^2) ----
    const float bia = bias[0];
    for (int r = wid; r < NN; r += 8){
        float t = 0.f;
        #pragma unroll
        for (int q = 0; q < 4; ++q){
            int m = lane + q * 32;
            t += AB[r * PA + m] * sh_dv[m];
        }
        #pragma unroll
        for (int o = 16; o; o >>= 1) t += __shfl_down_sync(~0u, t, o);
        if (!lane){
            t += sh_dv[r];
            float o1 = sh_coef[r] * t + bia;
            sh_alpha[r] = 1.f / (1.f + __expf(-(o1 * o1)));
        }
    }
    const int nuniq = __syncthreads_count((tid < NN) ? sh_flags[tid] : 0);

    // ---- cut = k-th largest alpha (tie-correct) ----
    if (nuniq > 1 && tid < NN){
        float a = sh_alpha[tid];
        int gt = 0, ge = 0;
        for (int j2 = 0; j2 < NN; ++j2){
            float aj = sh_alpha[j2];
            gt += (aj > a); ge += (aj >= a);
        }
        int k   = (nuniq + 9) / 10 + 1;
        int idx = min(k - 1, NN - 1);
        if (gt <= idx && idx < ge) sh_cut = a;
    }
    __syncthreads();
    if (tid < NN) sh_ca[tid] = fmaxf(sh_alpha[tid] + 1e-7f - sh_cut, 0.f);
    __syncthreads();

    // ---- SshT[j][r] = S[r][j] (row-r L1-normalized), tf32-rounded ----
    for (int r = wid; r < NN; r += 8){
        float c = sh_coef[r];
        float vals[4], ssum = 0.f;
        #pragma unroll
        for (int q = 0; q < 4; ++q){
            int j = lane + q * 32;
            float a = AB[r * PA + j] + ((j == r) ? 1.f : 0.f);
            float v = c * a * sh_dinv[j] * sh_ca[j];
            vals[q] = v; ssum += v;   // all terms nonneg
        }
        #pragma unroll
        for (int o = 16; o; o >>= 1) ssum += __shfl_xor_sync(~0u, ssum, o);
        float inv = 1.f / fmaxf(ssum, 1e-12f);
        #pragma unroll
        for (int q = 0; q < 4; ++q)
            Ssh[(lane + q * 32) * PS + r] = tf32r(vals[q] * inv);
    }
    __syncthreads();

    // ---- round adj to tf32 in place (prologue is done with fp32 adj) ----
    for (int u = tid; u < NN * NN; u += 256){
        int idx = (u >> 7) * PA + (u & 127);
        AB[idx] = tf32r(AB[idx]);
    }
    __syncthreads();

    const uint32_t* Su = (const uint32_t*)Ssh;
    const uint32_t* Au = (const uint32_t*)AB;
    const uint32_t* Xu = (const uint32_t*)XB;

    // =========== GEMM1: T1 = S^T @ adj (accs stay in registers) ===========
    float c1[2][8][4];
    #pragma unroll
    for (int s = 0; s < 2; ++s)
        #pragma unroll
        for (int jt = 0; jt < 8; ++jt)
            #pragma unroll
            for (int q = 0; q < 4; ++q) c1[s][jt][q] = 0.f;

    for (int ks = 0; ks < 16; ++ks){
        int m0 = ks * 8;
        uint32_t a[2][4];
        #pragma unroll
        for (int s = 0; s < 2; ++s){
            int r0 = i0 + s * 16 + g;
            a[s][0] = Su[r0 * PS + m0 + tg];
            a[s][1] = Su[(r0 + 8) * PS + m0 + tg];
            a[s][2] = Su[r0 * PS + m0 + tg + 4];
            a[s][3] = Su[(r0 + 8) * PS + m0 + tg + 4];
        }
        #pragma unroll
        for (int jt = 0; jt < 8; ++jt){
            int j = jh * 64 + jt * 8 + g;
            uint32_t b0 = Au[(m0 + tg) * PA + j];
            uint32_t b1 = Au[(m0 + tg + 4) * PA + j];
            MMA8(c1[0][jt], a[0], b0, b1);
            MMA8(c1[1][jt], a[1], b0, b1);
        }
    }
    __syncthreads();   // all GEMM1 reads of adj done

    // ---- store T1 (tf32) into the adj buffer, pitch PT ----
    float* T1 = AB;
    #pragma unroll
    for (int s = 0; s < 2; ++s)
        #pragma unroll
        for (int jt = 0; jt < 8; ++jt){
            int r0 = i0 + s * 16 + g, col = jh * 64 + jt * 8 + 2 * tg;
            *(float2*)(T1 + r0 * PT + col) =
                make_float2(tf32r(c1[s][jt][0]), tf32r(c1[s][jt][1]));
            *(float2*)(T1 + (r0 + 8) * PT + col) =
                make_float2(tf32r(c1[s][jt][2]), tf32r(c1[s][jt][3]));
        }
    __syncthreads();

    // =========== GEMM3: nadj = T1 @ S  (B[m][j] = S[m][j] = SshT[j][m]) ===========
    {
        float c3[2][8][4];
        #pragma unroll
        for (int s = 0; s < 2; ++s)
            #pragma unroll
            for (int jt = 0; jt < 8; ++jt)
                #pragma unroll
                for (int q = 0; q < 4; ++q) c3[s][jt][q] = 0.f;
        const uint32_t* Tu = (const uint32_t*)T1;
        for (int ks = 0; ks < 16; ++ks){
            int m0 = ks * 8;
            uint32_t a[2][4];
            #pragma unroll
            for (int s = 0; s < 2; ++s){
                int r0 = i0 + s * 16 + g;
                a[s][0] = Tu[r0 * PT + m0 + tg];
                a[s][1] = Tu[(r0 + 8) * PT + m0 + tg];
                a[s][2] = Tu[r0 * PT + m0 + tg + 4];
                a[s][3] = Tu[(r0 + 8) * PT + m0 + tg + 4];
            }
            #pragma unroll
            for (int jt = 0; jt < 8; ++jt){
                int j = jh * 64 + jt * 8 + g;
                uint32_t b0 = Su[j * PS + m0 + tg];
                uint32_t b1 = Su[j * PS + m0 + tg + 4];
                MMA8(c3[0][jt], a[0], b0, b1);
                MMA8(c3[1][jt], a[1], b0, b1);
            }
        }
        float* nb = nadj + (size_t)b * NN * NN;
        #pragma unroll
        for (int s = 0; s < 2; ++s)
            #pragma unroll
            for (int jt = 0; jt < 8; ++jt){
                int r0 = i0 + s * 16 + g, col = jh * 64 + jt * 8 + 2 * tg;
                *(float2*)(nb + r0 * NN + col)       = make_float2(c3[s][jt][0], c3[s][jt][1]);
                *(float2*)(nb + (r0 + 8) * NN + col) = make_float2(c3[s][jt][2], c3[s][jt][3]);
            }
    }

    // =========== GEMM2: emb = S^T @ X, two 128-wide d-tiles ===========
    #pragma unroll 1
    for (int t = 0; t < 2; ++t){
        if (t == 1){
            __syncthreads();   // tile-0 consumers done
            for (int u = tid; u < NN * 128; u += 256){
                int m = u >> 7, d = u & 127;
                XB[m * PA + d] = tf32r(xb[m * ND + 128 + d]);
            }
            __syncthreads();
        }
        float c2[2][8][4];
        #pragma unroll
        for (int s = 0; s < 2; ++s)
            #pragma unroll
            for (int jt = 0; jt < 8; ++jt)
                #pragma unroll
                for (int q = 0; q < 4; ++q) c2[s][jt][q] = 0.f;
        for (int ks = 0; ks < 16; ++ks){
            int m0 = ks * 8;
            uint32_t a[2][4];
            #pragma unroll
            for (int s = 0; s < 2; ++s){
                int r0 = i0 + s * 16 + g;
                a[s][0] = Su[r0 * PS + m0 + tg];
                a[s][1] = Su[(r0 + 8) * PS + m0 + tg];
                a[s][2] = Su[r0 * PS + m0 + tg + 4];
                a[s][3] = Su[(r0 + 8) * PS + m0 + tg + 4];
            }
            #pragma unroll
            for (int jt = 0; jt < 8; ++jt){
                int j = jh * 64 + jt * 8 + g;
                uint32_t b0 = Xu[(m0 + tg) * PA + j];
                uint32_t b1 = Xu[(m0 + tg + 4) * PA + j];
                MMA8(c2[0][jt], a[0], b0, b1);
                MMA8(c2[1][jt], a[1], b0, b1);
            }
        }
        float* eb = emb + (size_t)b * NN * ND + t * 128;
        #pragma unroll
        for (int s = 0; s < 2; ++s)
            #pragma unroll
            for (int jt = 0; jt < 8; ++jt){
                int r0 = i0 + s * 16 + g, col = jh * 64 + jt * 8 + 2 * tg;
                *(float2*)(eb + r0 * ND + col)       = make_float2(c2[s][jt][0], c2[s][jt][1]);
                *(float2*)(eb + (r0 + 8) * ND + col) = make_float2(c2[s][jt][2], c2[s][jt][3]);
            }
    }
}

extern "C" void kernel_launch(void* const* d_in, const int* in_sizes, int n_in,
                              void* d_out, int out_size) {
    const float* x    = (const float*)d_in[0];
    const float* adj  = (const float*)d_in[1];
    const int*   head = (const int*)d_in[2];
    const float* lw   = (const float*)d_in[3];
    const float* bias = (const float*)d_in[4];

    float* out  = (float*)d_out;
    float* emb  = out;                            // [B, N, D]
    float* nadj = out + (size_t)NB * NN * ND;     // [B, N, N]

    const int dsmem = (NN * PS + NN * PA + NN * PA) * 4;   // 206,848 B
    cudaFuncSetAttribute(kmain, cudaFuncAttributeMaxDynamicSharedMemorySize, dsmem);
    kmain<<<NB, 256, dsmem>>>(x, adj, head, lw, bias, emb, nadj);
}

// round 4
// speedup vs baseline: 2.7832x; 1.3863x over previous
#include <cuda_runtime.h>
#include <cstdint>

#define NB 512
#define NN 128
#define ND 256
#define NTH 512
#define PS 132   // SshT pitch: 132 % 32 == 4  -> frag bank = 4g+tg (distinct)
#define PA 136   // adj/X pitch: 136 % 32 == 8 -> frag bank = 8tg+g (distinct)
#define PT 132   // T1 pitch (reuses adj buffer)

static __device__ __forceinline__ float tf32r(float f){
    uint32_t r;
    asm("cvt.rna.tf32.f32 %0, %1;" : "=r"(r) : "f"(f));
    return __uint_as_float(r);
}

#define MMA8(C, A, B0, B1) \
    asm volatile("mma.sync.aligned.m16n8k8.row.col.f32.tf32.tf32.f32 " \
        "{%0,%1,%2,%3}, {%4,%5,%6,%7}, {%8,%9}, {%0,%1,%2,%3};" \
        : "+f"((C)[0]), "+f"((C)[1]), "+f"((C)[2]), "+f"((C)[3]) \
        : "r"((A)[0]), "r"((A)[1]), "r"((A)[2]), "r"((A)[3]), "r"(B0), "r"(B1))

__global__ __launch_bounds__(512, 1) void kmain(
    const float* __restrict__ x, const float* __restrict__ adj,
    const int* __restrict__ head, const float* __restrict__ lw,
    const float* __restrict__ bias, float* __restrict__ emb, float* __restrict__ nadj)
{
    extern __shared__ float sm[];
    float* Ssh = sm;               // SshT[j][m] = S[m][j], tf32, pitch PS
    float* AB  = sm + NN * PS;     // adj fp32 (pitch PA) -> later T1 tf32 (pitch PT)
    float* XB  = AB + NN * PA;     // X tile [128][128], tf32, pitch PA

    __shared__ float sh_w[ND];
    __shared__ float sh_dinv[NN], sh_coef[NN], sh_dv[NN], sh_alpha[NN], sh_ca[NN];
    __shared__ int   sh_flags[NN];
    __shared__ float sh_cut;

    const int b = blockIdx.x, tid = threadIdx.x;
    const int lane = tid & 31, wid = tid >> 5;
    const int g = lane >> 2, tg = lane & 3;      // mma fragment coords
    const int i0 = (wid >> 2) * 32;              // warp rows
    const int j0 = (wid & 3) * 32;               // warp cols

    const float* xb = x + (size_t)b * NN * ND;
    const float* ab = adj + (size_t)b * NN * NN;

    // ---- loads: adj (fp32), X tile 0 (tf32), weights, flag init ----
    for (int u = tid; u < NN * NN; u += 512) AB[(u >> 7) * PA + (u & 127)] = ab[u];
    for (int u = tid; u < NN * 128; u += 512){
        int m = u >> 7, d = u & 127;
        XB[m * PA + d] = tf32r(xb[m * ND + d]);
    }
    if (tid < ND) sh_w[tid] = lw[tid];
    if (tid < NN) sh_flags[tid] = 0;
    if (tid == 0) sh_cut = 0.f;
    __syncthreads();

    // unique-head marking (idempotent racy writes)
    sh_flags[head[(size_t)b * NTH + tid] & (NN - 1)] = 1;

    // ---- rowsum_r, v_r = x[r]·w ----
    for (int r = wid; r < NN; r += 16){
        float s = 0.f, rs = 0.f;
        #pragma unroll
        for (int q = 0; q < 8; ++q) s += xb[r * ND + lane + q * 32] * sh_w[lane + q * 32];
        #pragma unroll
        for (int q = 0; q < 4; ++q) rs += AB[r * PA + lane + q * 32];
        #pragma unroll
        for (int o = 16; o; o >>= 1){
            s  += __shfl_down_sync(~0u, s, o);
            rs += __shfl_down_sync(~0u, rs, o);
        }
        if (!lane){
            float di = rsqrtf(fmaxf(rs + 1.f, 1.f));
            sh_dinv[r] = di;
            sh_coef[r] = (rs > 0.f) ? di : 0.f;
            sh_dv[r]   = di * s;
        }
    }
    __syncthreads();

    // ---- alpha_r = sigmoid((coef_r*(adj[r]·dv + dv_r) + bias)^2) ----
    const float bia = bias[0];
    for (int r = wid; r < NN; r += 16){
        float t = 0.f;
        #pragma unroll
        for (int q = 0; q < 4; ++q){
            int m = lane + q * 32;
            t += AB[r * PA + m] * sh_dv[m];
        }
        #pragma unroll
        for (int o = 16; o; o >>= 1) t += __shfl_down_sync(~0u, t, o);
        if (!lane){
            t += sh_dv[r];
            float o1 = sh_coef[r] * t + bia;
            sh_alpha[r] = 1.f / (1.f + __expf(-(o1 * o1)));
        }
    }
    const int nuniq = __syncthreads_count((tid < NN) ? sh_flags[tid] : 0);

    // ---- cut = k-th largest alpha (tie-correct) ----
    if (nuniq > 1 && tid < NN){
        float a = sh_alpha[tid];
        int gt = 0, ge = 0;
        for (int j2 = 0; j2 < NN; ++j2){
            float aj = sh_alpha[j2];
            gt += (aj > a); ge += (aj >= a);
        }
        int k   = (nuniq + 9) / 10 + 1;
        int idx = min(k - 1, NN - 1);
        if (gt <= idx && idx < ge) sh_cut = a;
    }
    __syncthreads();
    if (tid < NN) sh_ca[tid] = fmaxf(sh_alpha[tid] + 1e-7f - sh_cut, 0.f);
    __syncthreads();

    // ---- SshT[j][r] = S[r][j] (row-r L1-normalized), tf32-rounded ----
    for (int r = wid; r < NN; r += 16){
        float c = sh_coef[r];
        float vals[4], ssum = 0.f;
        #pragma unroll
        for (int q = 0; q < 4; ++q){
            int j = lane + q * 32;
            float a = AB[r * PA + j] + ((j == r) ? 1.f : 0.f);
            float v = c * a * sh_dinv[j] * sh_ca[j];
            vals[q] = v; ssum += v;   // all terms nonneg
        }
        #pragma unroll
        for (int o = 16; o; o >>= 1) ssum += __shfl_xor_sync(~0u, ssum, o);
        float inv = 1.f / fmaxf(ssum, 1e-12f);
        #pragma unroll
        for (int q = 0; q < 4; ++q)
            Ssh[(lane + q * 32) * PS + r] = tf32r(vals[q] * inv);
    }
    __syncthreads();

    // ---- round adj to tf32 in place ----
    for (int u = tid; u < NN * NN; u += 512){
        int idx = (u >> 7) * PA + (u & 127);
        AB[idx] = tf32r(AB[idx]);
    }
    __syncthreads();

    const uint32_t* Su = (const uint32_t*)Ssh;
    const uint32_t* Au = (const uint32_t*)AB;
    const uint32_t* Xu = (const uint32_t*)XB;

    // =========== GEMM1: T1 = S^T @ adj (accs in registers) ===========
    float c1[2][4][4];
    #pragma unroll
    for (int s = 0; s < 2; ++s)
        #pragma unroll
        for (int jt = 0; jt < 4; ++jt)
            #pragma unroll
            for (int q = 0; q < 4; ++q) c1[s][jt][q] = 0.f;

    for (int ks = 0; ks < 16; ++ks){
        int m0 = ks * 8;
        uint32_t a[2][4];
        #pragma unroll
        for (int s = 0; s < 2; ++s){
            int r0 = i0 + s * 16 + g;
            a[s][0] = Su[r0 * PS + m0 + tg];
            a[s][1] = Su[(r0 + 8) * PS + m0 + tg];
            a[s][2] = Su[r0 * PS + m0 + tg + 4];
            a[s][3] = Su[(r0 + 8) * PS + m0 + tg + 4];
        }
        #pragma unroll
        for (int jt = 0; jt < 4; ++jt){
            int j = j0 + jt * 8 + g;
            uint32_t b0 = Au[(m0 + tg) * PA + j];
            uint32_t b1 = Au[(m0 + tg + 4) * PA + j];
            MMA8(c1[0][jt], a[0], b0, b1);
            MMA8(c1[1][jt], a[1], b0, b1);
        }
    }
    __syncthreads();   // all GEMM1 reads of adj done

    // ---- store T1 (tf32) into the adj buffer, pitch PT ----
    float* T1 = AB;
    #pragma unroll
    for (int s = 0; s < 2; ++s)
        #pragma unroll
        for (int jt = 0; jt < 4; ++jt){
            int r0 = i0 + s * 16 + g, col = j0 + jt * 8 + 2 * tg;
            *(float2*)(T1 + r0 * PT + col) =
                make_float2(tf32r(c1[s][jt][0]), tf32r(c1[s][jt][1]));
            *(float2*)(T1 + (r0 + 8) * PT + col) =
                make_float2(tf32r(c1[s][jt][2]), tf32r(c1[s][jt][3]));
        }
    __syncthreads();

    // =========== GEMM3: nadj = T1 @ S (B[m][j] = SshT[j][m]) ===========
    {
        float c3[2][4][4];
        #pragma unroll
        for (int s = 0; s < 2; ++s)
            #pragma unroll
            for (int jt = 0; jt < 4; ++jt)
                #pragma unroll
                for (int q = 0; q < 4; ++q) c3[s][jt][q] = 0.f;
        const uint32_t* Tu = (const uint32_t*)T1;
        for (int ks = 0; ks < 16; ++ks){
            int m0 = ks * 8;
            uint32_t a[2][4];
            #pragma unroll
            for (int s = 0; s < 2; ++s){
                int r0 = i0 + s * 16 + g;
                a[s][0] = Tu[r0 * PT + m0 + tg];
                a[s][1] = Tu[(r0 + 8) * PT + m0 + tg];
                a[s][2] = Tu[r0 * PT + m0 + tg + 4];
                a[s][3] = Tu[(r0 + 8) * PT + m0 + tg + 4];
            }
            #pragma unroll
            for (int jt = 0; jt < 4; ++jt){
                int j = j0 + jt * 8 + g;
                uint32_t b0 = Su[j * PS + m0 + tg];
                uint32_t b1 = Su[j * PS + m0 + tg + 4];
                MMA8(c3[0][jt], a[0], b0, b1);
                MMA8(c3[1][jt], a[1], b0, b1);
            }
        }
        float* nb = nadj + (size_t)b * NN * NN;
        #pragma unroll
        for (int s = 0; s < 2; ++s)
            #pragma unroll
            for (int jt = 0; jt < 4; ++jt){
                int r0 = i0 + s * 16 + g, col = j0 + jt * 8 + 2 * tg;
                *(float2*)(nb + r0 * NN + col)       = make_float2(c3[s][jt][0], c3[s][jt][1]);
                *(float2*)(nb + (r0 + 8) * NN + col) = make_float2(c3[s][jt][2], c3[s][jt][3]);
            }
    }

    // =========== GEMM2: emb = S^T @ X, two 128-wide d-tiles ===========
    #pragma unroll 1
    for (int t = 0; t < 2; ++t){
        if (t == 1){
            __syncthreads();   // tile-0 consumers done
            for (int u = tid; u < NN * 128; u += 512){
                int m = u >> 7, d = u & 127;
                XB[m * PA + d] = tf32r(xb[m * ND + 128 + d]);
            }
            __syncthreads();
        }
        float c2[2][4][4];
        #pragma unroll
        for (int s = 0; s < 2; ++s)
            #pragma unroll
            for (int jt = 0; jt < 4; ++jt)
                #pragma unroll
                for (int q = 0; q < 4; ++q) c2[s][jt][q] = 0.f;
        for (int ks = 0; ks < 16; ++ks){
            int m0 = ks * 8;
            uint32_t a[2][4];
            #pragma unroll
            for (int s = 0; s < 2; ++s){
                int r0 = i0 + s * 16 + g;
                a[s][0] = Su[r0 * PS + m0 + tg];
                a[s][1] = Su[(r0 + 8) * PS + m0 + tg];
                a[s][2] = Su[r0 * PS + m0 + tg + 4];
                a[s][3] = Su[(r0 + 8) * PS + m0 + tg + 4];
            }
            #pragma unroll
            for (int jt = 0; jt < 4; ++jt){
                int j = j0 + jt * 8 + g;
                uint32_t b0 = Xu[(m0 + tg) * PA + j];
                uint32_t b1 = Xu[(m0 + tg + 4) * PA + j];
                MMA8(c2[0][jt], a[0], b0, b1);
                MMA8(c2[1][jt], a[1], b0, b1);
            }
        }
        float* eb = emb + (size_t)b * NN * ND + t * 128;
        #pragma unroll
        for (int s = 0; s < 2; ++s)
            #pragma unroll
            for (int jt = 0; jt < 4; ++jt){
                int r0 = i0 + s * 16 + g, col = j0 + jt * 8 + 2 * tg;
                *(float2*)(eb + r0 * ND + col)       = make_float2(c2[s][jt][0], c2[s][jt][1]);
                *(float2*)(eb + (r0 + 8) * ND + col) = make_float2(c2[s][jt][2], c2[s][jt][3]);
            }
    }
}

extern "C" void kernel_launch(void* const* d_in, const int* in_sizes, int n_in,
                              void* d_out, int out_size) {
    const float* x    = (const float*)d_in[0];
    const float* adj  = (const float*)d_in[1];
    const int*   head = (const int*)d_in[2];
    const float* lw   = (const float*)d_in[3];
    const float* bias = (const float*)d_in[4];

    float* out  = (float*)d_out;
    float* emb  = out;                            // [B, N, D]
    float* nadj = out + (size_t)NB * NN * ND;     // [B, N, N]

    const int dsmem = (NN * PS + NN * PA + NN * PA) * 4;   // 206,848 B
    cudaFuncSetAttribute(kmain, cudaFuncAttributeMaxDynamicSharedMemorySize, dsmem);
    kmain<<<NB, 512, dsmem>>>(x, adj, head, lw, bias, emb, nadj);
}